// round 15
// baseline (speedup 1.0000x reference)
#include <cuda_runtime.h>
#include <math.h>

// ---------------- problem constants ----------------
#define NB    64        // batch
#define NN    1000      // nodes per sample
#define NTOT  64000     // NB*NN
#define SEQL  12
#define D1    4000      // NN*FEAT
#define H1S   256
#define H2S   128
#define G1    1024      // 4*H1S
#define G2    512       // 4*H2S
#define TBR   768       // SEQL*NB
#define EMAX  1024000
#define ETOTMAX (EMAX + NTOT)
#define SPLITK 10       // K=4000 -> klen=400, multiple of 16

typedef unsigned long long ull;

// ---------------- scratch (device globals; no allocation allowed) ----------------
__device__ __align__(256) float d_h[NTOT * 96];        // GAT hidden, [n][head][c]
__device__ __align__(256) float d_asrc[NTOT * 2];
__device__ __align__(256) float d_adst[NTOT * 2];
__device__ __align__(256) float d_den[NTOT * 2];       // segment sum of exp
__device__ __align__(256) float d_w[ETOTMAX * 2];      // softmax numerator exp(v)
// d_g: GAT output re-laid-out as the LSTM1 GEMM A-matrix:
// row m = b*SEQL + t (768 rows), col k = 4n+f (4000) -> fully contiguous rows.
__device__ __align__(256) float d_g[TBR * D1];
__device__ __align__(256) float d_wih1T[D1 * G1];      // Wih1 transposed [k][j]
__device__ __align__(256) float d_xw1[TBR * G1];       // LSTM1 input projection (no bias)
__device__ __align__(256) float d_whh1T[H1S * G1];
__device__ __align__(256) float d_whh2T[H2S * G2];
__device__ __align__(256) float d_wih2T[H1S * G2];
__device__ __align__(256) float d_ws[G1 * 4];          // col-sums of W_ih1 per (j, f)
// LSTM state block: [0,16384) h1 buf0 | [16384,32768) h1 buf1 |
// [32768,49152) c1 | [49152,57344) h2 | [57344,65536) c2   (all [unit][batch])
__device__ __align__(256) float d_state[65536];

// ---------------- helpers ----------------
__device__ __forceinline__ float sigf(float x) { return 1.f / (1.f + expf(-x)); }

// packed f32x2 FMA (FFMA2)
__device__ __forceinline__ void fma2(ull& acc, ull a, ull b) {
    asm("fma.rn.f32x2 %0, %1, %2, %0;" : "+l"(acc) : "l"(a), "l"(b));
}
__device__ __forceinline__ ull pack2(float x, float y) {
    ull r; asm("mov.b64 %0, {%1, %2};" : "=l"(r) : "f"(x), "f"(y)); return r;
}
__device__ __forceinline__ float2 unpack2(ull v) {
    float2 r; asm("mov.b64 {%0, %1}, %2;" : "=f"(r.x), "=f"(r.y) : "l"(v)); return r;
}
__device__ __forceinline__ void redv4(float* dst, float a, float b, float c, float d) {
    asm volatile("red.global.add.v4.f32 [%0], {%1, %2, %3, %4};"
                 :: "l"(dst), "f"(a), "f"(b), "f"(c), "f"(d) : "memory");
}
__device__ __forceinline__ void redv2(float* dst, float a, float b) {
    asm volatile("red.global.add.v2.f32 [%0], {%1, %2};"
                 :: "l"(dst), "f"(a), "f"(b) : "memory");
}

// ===== GAT projection + attention + zero-init + Wih1 transpose =====
// Blocks 0..999: 64 nodes each (GEMM + attention + zero-init).
// Blocks 1000..1124: smem-tiled transpose Wih1 -> d_wih1T (k-tile c = blk-1000).
__global__ __launch_bounds__(256) void k_gemm_attn(
    const float* __restrict__ x, const float* __restrict__ Wg,
    const float* __restrict__ att_s, const float* __restrict__ att_d,
    const float* __restrict__ Wih1)
{
    __shared__ __align__(16) float xs[48][68];   // [k][node]; also reused as transpose tile
    __shared__ __align__(16) float ws[48][96];   // [k][col]
    __shared__ float als[96], ald[96];
    __shared__ float red1[64][17], red2[64][17];
    int tid = threadIdx.x;

    if (blockIdx.x >= NTOT / 64) {
        // ---- Wih1 transpose: k-range [c*32, c*32+32), all j ----
        int c = blockIdx.x - NTOT / 64;          // 0..124
        int k0 = c * 32;
        float* ts = &xs[0][0];                   // 32x32 tile, stride 33
        int jl = tid >> 5, kl = tid & 31;
        for (int j0 = 0; j0 < G1; j0 += 32) {
            __syncthreads();
#pragma unroll
            for (int i = 0; i < 4; i++)
                ts[(jl + i * 8) * 33 + kl] =
                    __ldg(Wih1 + (size_t)(j0 + jl + i * 8) * D1 + k0 + kl);
            __syncthreads();
#pragma unroll
            for (int i = 0; i < 4; i++) {
                int kl2 = (tid >> 5) + i * 8, jl2 = tid & 31;
                d_wih1T[(size_t)(k0 + kl2) * G1 + j0 + jl2] = ts[jl2 * 33 + kl2];
            }
        }
        return;
    }

    int n0 = blockIdx.x * 64;

    // ---- folded zero-init ----
    for (int i = tid; i < 64 * 48; i += 256) d_g[(size_t)n0 * 48 + i] = 0.f;
    if (tid < 128) d_den[n0 * 2 + tid] = 0.f;
    if (blockIdx.x < TBR)
        for (int i = tid; i < G1; i += 256) d_xw1[(size_t)blockIdx.x * G1 + i] = 0.f;
    if (blockIdx.x >= 900 && blockIdx.x < 1000)
        for (int i = (blockIdx.x - 900) * 256 + tid; i < 65536; i += 100 * 256)
            d_state[i] = 0.f;

    for (int i = tid; i < 48 * 96 / 4; i += 256) {
        float4 v = ((const float4*)Wg)[i];
        int k = i / 24, j = (i % 24) * 4;
        *(float4*)&ws[k][j] = v;
    }
    if (tid < 96) { als[tid] = __ldg(att_s + tid); ald[tid] = __ldg(att_d + tid); }
    for (int i = tid; i < 64 * 12; i += 256) {
        int node = i / 12, kq = i % 12;
        float4 v = ((const float4*)(x + (size_t)(n0 + node) * 48))[kq];
        xs[kq * 4 + 0][node] = v.x; xs[kq * 4 + 1][node] = v.y;
        xs[kq * 4 + 2][node] = v.z; xs[kq * 4 + 3][node] = v.w;
    }
    __syncthreads();

    int tx = tid & 15, ty = tid >> 4;
    int c0 = tx * 6;
    ull acc[4][3];
#pragma unroll
    for (int i = 0; i < 4; i++)
#pragma unroll
        for (int p = 0; p < 3; p++) acc[i][p] = 0ULL;

#pragma unroll 4
    for (int k = 0; k < 48; k++) {
        float4 a = *(const float4*)&xs[k][ty * 4];
        const ull* bp = (const ull*)&ws[k][c0];
        ull b0 = bp[0], b1 = bp[1], b2 = bp[2];
        ull a0 = pack2(a.x, a.x), a1 = pack2(a.y, a.y);
        ull a2 = pack2(a.z, a.z), a3 = pack2(a.w, a.w);
        fma2(acc[0][0], a0, b0); fma2(acc[0][1], a0, b1); fma2(acc[0][2], a0, b2);
        fma2(acc[1][0], a1, b0); fma2(acc[1][1], a1, b1); fma2(acc[1][2], a1, b2);
        fma2(acc[2][0], a2, b0); fma2(acc[2][1], a2, b1); fma2(acc[2][2], a2, b2);
        fma2(acc[3][0], a3, b0); fma2(acc[3][1], a3, b1); fma2(acc[3][2], a3, b2);
    }

#pragma unroll
    for (int i = 0; i < 4; i++) {
        int node = ty * 4 + i;
        float s1 = 0.f, s2 = 0.f;
#pragma unroll
        for (int p = 0; p < 3; p++) {
            float2 hv = unpack2(acc[i][p]);
            int c = c0 + p * 2;
            s1 = fmaf(hv.x, als[c], fmaf(hv.y, als[c + 1], s1));
            s2 = fmaf(hv.x, ald[c], fmaf(hv.y, ald[c + 1], s2));
            *(float2*)(d_h + (size_t)(n0 + node) * 96 + c) = hv;
        }
        red1[node][tx] = s1;
        red2[node][tx] = s2;
    }
    __syncthreads();
    if (tid < 128) {
        int node = tid & 63, head = tid >> 6;
        float s1 = 0.f, s2 = 0.f;
#pragma unroll
        for (int q = 0; q < 8; q++) {
            s1 += red1[node][head * 8 + q];
            s2 += red2[node][head * 8 + q];
        }
        d_asrc[(size_t)(n0 + node) * 2 + head] = s1;
        d_adst[(size_t)(n0 + node) * 2 + head] = s2;
    }
}

// edge_index arrives as int32 (JAX x64 disabled)
__device__ __forceinline__ void edge_sd(const int* __restrict__ ei, int E, int e,
                                        int& s, int& d) {
    if (e < E) { s = ei[e]; d = ei[E + e]; }
    else       { s = e - E; d = s; }
}

// Softmax without max-subtraction (|v| <~ 1; math-identical).
__global__ void k_passAB(const int* __restrict__ ei, int E) {
    int e = blockIdx.x * blockDim.x + threadIdx.x;
    int etot = E + NTOT;
    if (e >= etot) return;
    int s, d; edge_sd(ei, E, e, s, d);
    float2 as = *(const float2*)(d_asrc + (size_t)s * 2);
    float2 ad = *(const float2*)(d_adst + (size_t)d * 2);
    float v0 = as.x + ad.x; v0 = v0 > 0.f ? v0 : 0.2f * v0;
    float v1 = as.y + ad.y; v1 = v1 > 0.f ? v1 : 0.2f * v1;
    float w0 = expf(v0), w1 = expf(v1);
    *(float2*)(d_w + (size_t)e * 2) = make_float2(w0, w1);
    redv2(d_den + (size_t)d * 2, w0, w1);
}

// Scatter into A-matrix layout: g[(b*SEQL + q)*NN + n][f], q == t.
__global__ void k_passC(const int* __restrict__ ei, int E) {
    int idx = blockIdx.x * blockDim.x + threadIdx.x;
    int etot = E + NTOT;
    if (idx >= etot * 12) return;
    int e = idx / 12, q = idx - e * 12;
    int s, d; edge_sd(ei, E, e, s, d);
    float2 a  = *(const float2*)(d_w + (size_t)e * 2);
    float2 dn = *(const float2*)(d_den + (size_t)d * 2);
    float a0 = a.x * __fdividef(0.5f, dn.x + 1e-16f);
    float a1 = a.y * __fdividef(0.5f, dn.y + 1e-16f);
    const float4 h0 = *(const float4*)(d_h + (size_t)s * 96 + q * 4);
    const float4 h1 = *(const float4*)(d_h + (size_t)s * 96 + 48 + q * 4);
    float vx = fmaf(a0, h0.x, a1 * h1.x);
    float vy = fmaf(a0, h0.y, a1 * h1.y);
    float vz = fmaf(a0, h0.z, a1 * h1.z);
    float vw = fmaf(a0, h0.w, a1 * h1.w);
    int b = d / NN, n = d - b * NN;
    redv4(d_g + (((size_t)(b * SEQL + q)) * NN + n) * 4, vx, vy, vz, vw);
}

// NT SGEMM v2: A = d_g (768x4000, contiguous rows), B = d_wih1T ([k][j], coalesced).
// C = d_xw1 (zeroed), split-K via blockIdx.z, red-v4 epilogue. Row m = b*SEQL+t.
__global__ void k_sgemm1() {
    const int K = D1, N = G1;
    __shared__ __align__(16) float As[16][68];   // stride 68: 16B-aligned rows
    __shared__ __align__(16) float Bs[16][68];
    int t = threadIdx.x;
    int ty = t >> 3;              // 0..15
    int tx = t & 7;               // 0..7
    int m0 = blockIdx.y * 64;
    int n0 = blockIdx.x * 64;
    int klen = K / SPLITK;        // 400
    int kbeg = blockIdx.z * klen;

    ull acc2[4][4];
#pragma unroll
    for (int i = 0; i < 4; i++)
#pragma unroll
        for (int j = 0; j < 4; j++) acc2[i][j] = 0ULL;

    for (int k0 = kbeg; k0 < kbeg + klen; k0 += 16) {
#pragma unroll
        for (int l = 0; l < 2; l++) {
            int lin = t + l * 128;        // 0..255
            // A: row mm (64), 4 float4 chunks along k -> coalesced 64B/row
            int mm = lin >> 2, kq = lin & 3;
            float4 av = *(const float4*)(d_g + (size_t)(m0 + mm) * K + k0 + kq * 4);
            As[kq * 4 + 0][mm] = av.x; As[kq * 4 + 1][mm] = av.y;
            As[kq * 4 + 2][mm] = av.z; As[kq * 4 + 3][mm] = av.w;
            // B: row kk (16), 16 float4 chunks along j -> coalesced 256B/row
            int kk = lin >> 4, nq = lin & 15;
            float4 bv = *(const float4*)(d_wih1T + (size_t)(k0 + kk) * N + n0 + nq * 4);
            *(float4*)&Bs[kk][nq * 4] = bv;
        }
        __syncthreads();
#pragma unroll
        for (int kk = 0; kk < 16; kk++) {
            float4 a = *(const float4*)&As[kk][ty * 4];
            ull ad0 = pack2(a.x, a.x), ad1 = pack2(a.y, a.y);
            ull ad2 = pack2(a.z, a.z), ad3 = pack2(a.w, a.w);
            ulonglong2 bA = *(const ulonglong2*)&Bs[kk][tx * 8];
            ulonglong2 bB = *(const ulonglong2*)&Bs[kk][tx * 8 + 4];
            ull b0 = bA.x, b1 = bA.y, b2 = bB.x, b3 = bB.y;
            fma2(acc2[0][0], ad0, b0); fma2(acc2[0][1], ad0, b1);
            fma2(acc2[0][2], ad0, b2); fma2(acc2[0][3], ad0, b3);
            fma2(acc2[1][0], ad1, b0); fma2(acc2[1][1], ad1, b1);
            fma2(acc2[1][2], ad1, b2); fma2(acc2[1][3], ad1, b3);
            fma2(acc2[2][0], ad2, b0); fma2(acc2[2][1], ad2, b1);
            fma2(acc2[2][2], ad2, b2); fma2(acc2[2][3], ad2, b3);
            fma2(acc2[3][0], ad3, b0); fma2(acc2[3][1], ad3, b1);
            fma2(acc2[3][2], ad3, b2); fma2(acc2[3][3], ad3, b3);
        }
        __syncthreads();
    }
#pragma unroll
    for (int i = 0; i < 4; i++) {
        int m = m0 + ty * 4 + i;
        float* cr = d_xw1 + (size_t)m * N + n0 + tx * 8;
        float2 u0 = unpack2(acc2[i][0]), u1 = unpack2(acc2[i][1]);
        float2 u2 = unpack2(acc2[i][2]), u3 = unpack2(acc2[i][3]);
        redv4(cr,     u0.x, u0.y, u1.x, u1.y);
        redv4(cr + 4, u2.x, u2.y, u3.x, u3.y);
    }
}

// Prep: W_ih1 col-sums (blocks < G1) + recurrent weight transposes (rest).
__global__ void k_prep(const float* __restrict__ Wih1, const float* __restrict__ W1,
                       const float* __restrict__ W2, const float* __restrict__ W3) {
    if (blockIdx.x < G1) {
        __shared__ float part[256];
        int j = blockIdx.x;
        const float* wr = Wih1 + (size_t)j * D1;
        float acc = 0.f;
        for (int e = threadIdx.x; e < D1; e += 256) acc += __ldg(wr + e);  // f = e&3 fixed
        part[threadIdx.x] = acc;
        __syncthreads();
        if (threadIdx.x < 4) {
            float s = 0.f;
            for (int i = threadIdx.x; i < 256; i += 4) s += part[i];
            d_ws[j * 4 + threadIdx.x] = s;
        }
        return;
    }
    int idx = (blockIdx.x - G1) * 256 + threadIdx.x;
    if (idx < G1 * H1S) {                                   // whh1T
        int k = idx / G1, j = idx % G1;
        d_whh1T[idx] = W1[(size_t)j * H1S + k];
    } else if (idx < G1 * H1S + G2 * H2S) {                 // whh2T
        int r = idx - G1 * H1S;
        int k = r / G2, j = r % G2;
        d_whh2T[r] = W2[(size_t)j * H2S + k];
    } else if (idx < G1 * H1S + G2 * H2S + G2 * H1S) {      // wih2T
        int r = idx - G1 * H1S - G2 * H2S;
        int k = r / G2, j = r % G2;
        d_wih2T[r] = W3[(size_t)j * H1S + k];
    }
}

// ============ pipelined LSTM: launch s runs step1(t=s) [blocks 0..63] and
// step2(t=s-1) [blocks 64..95] concurrently. h1 double-buffered by t parity. ====
__global__ __launch_bounds__(256) void k_pipe(
    int s, const float* __restrict__ b1, const float* __restrict__ gbias,
    const float* __restrict__ b2v)
{
    __shared__ __align__(16) float hs1[H1S][16];
    __shared__ __align__(16) float hs2[H2S][16];
    __shared__ float gsm[64][17];
    int tid = threadIdx.x;

    if (blockIdx.x < 64) {
        // ---------- layer 1, t = s ----------
        if (s >= SEQL) return;
        int t = s;
        int u0 = (blockIdx.x & 15) * 16;
        int b0 = (blockIdx.x >> 4) * 16;
        const float* hR = d_state + (t & 1) * (H1S * NB);
        float*       hW = d_state + ((t + 1) & 1) * (H1S * NB);
        float*       c1 = d_state + 2 * (H1S * NB);

        for (int i = tid; i < H1S * 16; i += 256)
            hs1[i >> 4][i & 15] = hR[(i >> 4) * NB + b0 + (i & 15)];
        __syncthreads();

        int jj = tid & 63, bq = tid >> 6;
        int j = (jj >> 4) * H1S + u0 + (jj & 15);
        ull a01 = 0, a23 = 0;
        const float* wp = d_whh1T + j;
#pragma unroll 8
        for (int k = 0; k < H1S; k++) {
            float w = wp[k * G1];
            ull wd = pack2(w, w);
            const ull* hp = (const ull*)&hs1[k][bq * 4];
            fma2(a01, wd, hp[0]);
            fma2(a23, wd, hp[1]);
        }
        {
            float bias = __ldg(b1 + j);
            float4 wsv = *(const float4*)(d_ws + j * 4);
            float4 gb  = *(const float4*)(gbias + 4 * t);
            bias = fmaf(gb.x, wsv.x, fmaf(gb.y, wsv.y,
                   fmaf(gb.z, wsv.z, fmaf(gb.w, wsv.w, bias))));
            float2 u01 = unpack2(a01), u23 = unpack2(a23);
            float gv4[4] = {u01.x, u01.y, u23.x, u23.y};
#pragma unroll
            for (int i = 0; i < 4; i++) {
                int b = b0 + bq * 4 + i;
                gsm[jj][bq * 4 + i] = gv4[i] + bias
                                    + d_xw1[((size_t)(b * SEQL + t)) * G1 + j];
            }
        }
        __syncthreads();
        {
            int bl = tid & 15, ul = tid >> 4;
            float iv = sigf(gsm[ul][bl]);
            float fv = sigf(gsm[16 + ul][bl]);
            float gv = tanhf(gsm[32 + ul][bl]);
            float ov = sigf(gsm[48 + ul][bl]);
            int ci = (u0 + ul) * NB + b0 + bl;
            float c = fv * c1[ci] + iv * gv;
            c1[ci] = c;
            hW[ci] = ov * tanhf(c);
        }
    } else {
        // ---------- layer 2, t = s-1 ----------
        if (s < 1) return;
        int t = s - 1;
        int r = blockIdx.x - 64;
        int u0 = (r & 7) * 16;
        int b0 = (r >> 3) * 16;
        const float* h1v = d_state + ((t + 1) & 1) * (H1S * NB);
        float*       h2  = d_state + 3 * (H1S * NB);
        float*       c2  = d_state + 3 * (H1S * NB) + H2S * NB;

        for (int i = tid; i < H1S * 16; i += 256)
            hs1[i >> 4][i & 15] = h1v[(i >> 4) * NB + b0 + (i & 15)];
        for (int i = tid; i < H2S * 16; i += 256)
            hs2[i >> 4][i & 15] = h2[(i >> 4) * NB + b0 + (i & 15)];
        __syncthreads();

        int jj = tid & 63, bq = tid >> 6;
        int j = (jj >> 4) * H2S + u0 + (jj & 15);
        ull a01 = 0, a23 = 0;
        const float* wp = d_wih2T + j;
#pragma unroll 8
        for (int k = 0; k < H1S; k++) {
            float w = wp[k * G2];
            ull wd = pack2(w, w);
            const ull* hp = (const ull*)&hs1[k][bq * 4];
            fma2(a01, wd, hp[0]);
            fma2(a23, wd, hp[1]);
        }
        const float* wq = d_whh2T + j;
#pragma unroll 8
        for (int k = 0; k < H2S; k++) {
            float w = wq[k * G2];
            ull wd = pack2(w, w);
            const ull* hp = (const ull*)&hs2[k][bq * 4];
            fma2(a01, wd, hp[0]);
            fma2(a23, wd, hp[1]);
        }
        {
            float bb = __ldg(b2v + j);
            float2 u01 = unpack2(a01), u23 = unpack2(a23);
            gsm[jj][bq * 4 + 0] = u01.x + bb;
            gsm[jj][bq * 4 + 1] = u01.y + bb;
            gsm[jj][bq * 4 + 2] = u23.x + bb;
            gsm[jj][bq * 4 + 3] = u23.y + bb;
        }
        __syncthreads();
        {
            int bl = tid & 15, ul = tid >> 4;
            float iv = sigf(gsm[ul][bl]);
            float fv = sigf(gsm[16 + ul][bl]);
            float gv = tanhf(gsm[32 + ul][bl]);
            float ov = sigf(gsm[48 + ul][bl]);
            int ci = (u0 + ul) * NB + b0 + bl;
            float c = fv * c2[ci] + iv * gv;
            c2[ci] = c;
            h2[ci] = ov * tanhf(c);
        }
    }
}

// out[b*2000 + j] = sum_k h2[k][b] * W_out[j,k] + b_out[j]
__global__ void k_out(const float* __restrict__ Wo, const float* __restrict__ bo,
                      float* __restrict__ out) {
    __shared__ __align__(16) float hr[H2S];
    const float* h2 = d_state + 3 * (H1S * NB);
    int b = blockIdx.y;
    if (threadIdx.x < H2S) hr[threadIdx.x] = h2[threadIdx.x * NB + b];
    __syncthreads();
    int j = blockIdx.x * blockDim.x + threadIdx.x;
    if (j >= NN * 2) return;
    const ull* wp = (const ull*)(Wo + (size_t)j * H2S);
    const ull* hp = (const ull*)hr;
    ull accA = 0, accB = 0;
#pragma unroll 8
    for (int k = 0; k < H2S / 2; k += 2) {
        fma2(accA, hp[k], wp[k]);
        fma2(accB, hp[k + 1], wp[k + 1]);
    }
    float2 uA = unpack2(accA), uB = unpack2(accB);
    out[(size_t)b * (NN * 2) + j] = uA.x + uA.y + uB.x + uB.y + __ldg(bo + j);
}

// ---------------- launch ----------------
extern "C" void kernel_launch(void* const* d_in, const int* in_sizes, int n_in,
                              void* d_out, int out_size) {
    const float* x     = (const float*)d_in[0];
    const int*   ei    = (const int*)d_in[1];     // int32 (JAX x64 disabled)
    const float* Wg    = (const float*)d_in[2];
    const float* att_s = (const float*)d_in[3];
    const float* att_d = (const float*)d_in[4];
    const float* gbias = (const float*)d_in[5];
    const float* Wih1  = (const float*)d_in[6];
    const float* Whh1  = (const float*)d_in[7];
    const float* b1    = (const float*)d_in[8];
    const float* Wih2  = (const float*)d_in[9];
    const float* Whh2  = (const float*)d_in[10];
    const float* b2    = (const float*)d_in[11];
    const float* Wo    = (const float*)d_in[12];
    const float* bo    = (const float*)d_in[13];
    float* out = (float*)d_out;

    int E = in_sizes[1] / 2;
    if (E > EMAX) E = EMAX;
    int etot = E + NTOT;

    // ncu captures launch #4 -> k_sgemm1 (v2) profiled: verify L1% drop.
    k_gemm_attn<<<NTOT / 64 + 125, 256>>>(x, Wg, att_s, att_d, Wih1); // 1
    k_passAB<<<(etot + 255) / 256, 256>>>(ei, E);                     // 2
    k_passC<<<(etot * 12 + 255) / 256, 256>>>(ei, E);                 // 3
    k_sgemm1<<<dim3(G1 / 64, TBR / 64, SPLITK), 128>>>();             // 4  <- profiled

    int tblocks = (G1 * H1S + G2 * H2S + G2 * H1S + 255) / 256;
    k_prep<<<G1 + tblocks, 256>>>(Wih1, Whh1, Whh2, Wih2);            // 5

    for (int s = 0; s <= SEQL; s++)                                   // 6..18
        k_pipe<<<96, 256>>>(s, b1, gbias, b2);

    k_out<<<dim3((NN * 2 + 255) / 256, NB), 256>>>(Wo, bo, out);      // 19
}

// round 16
// speedup vs baseline: 1.1893x; 1.1893x over previous
#include <cuda_runtime.h>
#include <math.h>

// ---------------- problem constants ----------------
#define NB    64        // batch
#define NN    1000      // nodes per sample
#define NTOT  64000     // NB*NN
#define SEQL  12
#define D1    4000      // NN*FEAT
#define H1S   256
#define H2S   128
#define G1    1024      // 4*H1S
#define G2    512       // 4*H2S
#define TBR   768       // SEQL*NB
#define EMAX  1024000
#define ETOTMAX (EMAX + NTOT)
#define SPLITK 10       // K=4000 -> klen=400, multiple of 16

typedef unsigned long long ull;

// ---------------- scratch (device globals; no allocation allowed) ----------------
__device__ __align__(256) float d_h[NTOT * 96];        // GAT hidden, [n][head][c]
__device__ __align__(256) float d_asrc[NTOT * 2];
__device__ __align__(256) float d_adst[NTOT * 2];
__device__ __align__(256) float d_den[NTOT * 2];       // segment sum of exp
__device__ __align__(256) float d_w[ETOTMAX * 2];      // softmax numerator exp(v)
__device__ __align__(256) float d_g[NTOT * 48];        // GAT out, [node][48] (passC-friendly)
__device__ __align__(256) float d_xin[TBR * D1];       // A-matrix: row m=b*12+t, contiguous
__device__ __align__(256) float d_wih1T[D1 * G1];      // Wih1 transposed [k][j]
__device__ __align__(256) float d_xw1[TBR * G1];       // LSTM1 input projection (no bias)
__device__ __align__(256) float d_whh1T[H1S * G1];
__device__ __align__(256) float d_whh2T[H2S * G2];
__device__ __align__(256) float d_wih2T[H1S * G2];
__device__ __align__(256) float d_ws[G1 * 4];          // col-sums of W_ih1 per (j, f)
// LSTM state block: [0,16384) h1 buf0 | [16384,32768) h1 buf1 |
// [32768,49152) c1 | [49152,57344) h2 | [57344,65536) c2   (all [unit][batch])
__device__ __align__(256) float d_state[65536];

// ---------------- helpers ----------------
__device__ __forceinline__ float sigf(float x) { return 1.f / (1.f + expf(-x)); }

// packed f32x2 FMA (FFMA2)
__device__ __forceinline__ void fma2(ull& acc, ull a, ull b) {
    asm("fma.rn.f32x2 %0, %1, %2, %0;" : "+l"(acc) : "l"(a), "l"(b));
}
__device__ __forceinline__ ull pack2(float x, float y) {
    ull r; asm("mov.b64 %0, {%1, %2};" : "=l"(r) : "f"(x), "f"(y)); return r;
}
__device__ __forceinline__ float2 unpack2(ull v) {
    float2 r; asm("mov.b64 {%0, %1}, %2;" : "=f"(r.x), "=f"(r.y) : "l"(v)); return r;
}
__device__ __forceinline__ void redv4(float* dst, float a, float b, float c, float d) {
    asm volatile("red.global.add.v4.f32 [%0], {%1, %2, %3, %4};"
                 :: "l"(dst), "f"(a), "f"(b), "f"(c), "f"(d) : "memory");
}
__device__ __forceinline__ void redv2(float* dst, float a, float b) {
    asm volatile("red.global.add.v2.f32 [%0], {%1, %2};"
                 :: "l"(dst), "f"(a), "f"(b) : "memory");
}

// ===== GAT projection + attention + zero-init + Wih1 transpose =====
// Blocks 0..999: 64 nodes each (GEMM + attention + zero-init).
// Blocks 1000..1124: smem-tiled transpose Wih1 -> d_wih1T (k-tile c = blk-1000).
__global__ __launch_bounds__(256) void k_gemm_attn(
    const float* __restrict__ x, const float* __restrict__ Wg,
    const float* __restrict__ att_s, const float* __restrict__ att_d,
    const float* __restrict__ Wih1)
{
    __shared__ __align__(16) float xs[48][68];   // [k][node]; also reused as transpose tile
    __shared__ __align__(16) float ws[48][96];   // [k][col]
    __shared__ float als[96], ald[96];
    __shared__ float red1[64][17], red2[64][17];
    int tid = threadIdx.x;

    if (blockIdx.x >= NTOT / 64) {
        // ---- Wih1 transpose: k-range [c*32, c*32+32), all j ----
        int c = blockIdx.x - NTOT / 64;          // 0..124
        int k0 = c * 32;
        float* ts = &xs[0][0];                   // 32x32 tile, stride 33
        int jl = tid >> 5, kl = tid & 31;
        for (int j0 = 0; j0 < G1; j0 += 32) {
            __syncthreads();
#pragma unroll
            for (int i = 0; i < 4; i++)
                ts[(jl + i * 8) * 33 + kl] =
                    __ldg(Wih1 + (size_t)(j0 + jl + i * 8) * D1 + k0 + kl);
            __syncthreads();
#pragma unroll
            for (int i = 0; i < 4; i++) {
                int kl2 = (tid >> 5) + i * 8, jl2 = tid & 31;
                d_wih1T[(size_t)(k0 + kl2) * G1 + j0 + jl2] = ts[jl2 * 33 + kl2];
            }
        }
        return;
    }

    int n0 = blockIdx.x * 64;

    // ---- folded zero-init ----
    for (int i = tid; i < 64 * 48; i += 256) d_g[(size_t)n0 * 48 + i] = 0.f;
    if (tid < 128) d_den[n0 * 2 + tid] = 0.f;
    if (blockIdx.x < TBR)
        for (int i = tid; i < G1; i += 256) d_xw1[(size_t)blockIdx.x * G1 + i] = 0.f;
    if (blockIdx.x >= 900 && blockIdx.x < 1000)
        for (int i = (blockIdx.x - 900) * 256 + tid; i < 65536; i += 100 * 256)
            d_state[i] = 0.f;

    for (int i = tid; i < 48 * 96 / 4; i += 256) {
        float4 v = ((const float4*)Wg)[i];
        int k = i / 24, j = (i % 24) * 4;
        *(float4*)&ws[k][j] = v;
    }
    if (tid < 96) { als[tid] = __ldg(att_s + tid); ald[tid] = __ldg(att_d + tid); }
    for (int i = tid; i < 64 * 12; i += 256) {
        int node = i / 12, kq = i % 12;
        float4 v = ((const float4*)(x + (size_t)(n0 + node) * 48))[kq];
        xs[kq * 4 + 0][node] = v.x; xs[kq * 4 + 1][node] = v.y;
        xs[kq * 4 + 2][node] = v.z; xs[kq * 4 + 3][node] = v.w;
    }
    __syncthreads();

    int tx = tid & 15, ty = tid >> 4;
    int c0 = tx * 6;
    ull acc[4][3];
#pragma unroll
    for (int i = 0; i < 4; i++)
#pragma unroll
        for (int p = 0; p < 3; p++) acc[i][p] = 0ULL;

#pragma unroll 4
    for (int k = 0; k < 48; k++) {
        float4 a = *(const float4*)&xs[k][ty * 4];
        const ull* bp = (const ull*)&ws[k][c0];
        ull b0 = bp[0], b1 = bp[1], b2 = bp[2];
        ull a0 = pack2(a.x, a.x), a1 = pack2(a.y, a.y);
        ull a2 = pack2(a.z, a.z), a3 = pack2(a.w, a.w);
        fma2(acc[0][0], a0, b0); fma2(acc[0][1], a0, b1); fma2(acc[0][2], a0, b2);
        fma2(acc[1][0], a1, b0); fma2(acc[1][1], a1, b1); fma2(acc[1][2], a1, b2);
        fma2(acc[2][0], a2, b0); fma2(acc[2][1], a2, b1); fma2(acc[2][2], a2, b2);
        fma2(acc[3][0], a3, b0); fma2(acc[3][1], a3, b1); fma2(acc[3][2], a3, b2);
    }

#pragma unroll
    for (int i = 0; i < 4; i++) {
        int node = ty * 4 + i;
        float s1 = 0.f, s2 = 0.f;
#pragma unroll
        for (int p = 0; p < 3; p++) {
            float2 hv = unpack2(acc[i][p]);
            int c = c0 + p * 2;
            s1 = fmaf(hv.x, als[c], fmaf(hv.y, als[c + 1], s1));
            s2 = fmaf(hv.x, ald[c], fmaf(hv.y, ald[c + 1], s2));
            *(float2*)(d_h + (size_t)(n0 + node) * 96 + c) = hv;
        }
        red1[node][tx] = s1;
        red2[node][tx] = s2;
    }
    __syncthreads();
    if (tid < 128) {
        int node = tid & 63, head = tid >> 6;
        float s1 = 0.f, s2 = 0.f;
#pragma unroll
        for (int q = 0; q < 8; q++) {
            s1 += red1[node][head * 8 + q];
            s2 += red2[node][head * 8 + q];
        }
        d_asrc[(size_t)(n0 + node) * 2 + head] = s1;
        d_adst[(size_t)(n0 + node) * 2 + head] = s2;
    }
}

// edge_index arrives as int32 (JAX x64 disabled)
__device__ __forceinline__ void edge_sd(const int* __restrict__ ei, int E, int e,
                                        int& s, int& d) {
    if (e < E) { s = ei[e]; d = ei[E + e]; }
    else       { s = e - E; d = s; }
}

// Softmax without max-subtraction (|v| <~ 1; math-identical).
__global__ void k_passAB(const int* __restrict__ ei, int E) {
    int e = blockIdx.x * blockDim.x + threadIdx.x;
    int etot = E + NTOT;
    if (e >= etot) return;
    int s, d; edge_sd(ei, E, e, s, d);
    float2 as = *(const float2*)(d_asrc + (size_t)s * 2);
    float2 ad = *(const float2*)(d_adst + (size_t)d * 2);
    float v0 = as.x + ad.x; v0 = v0 > 0.f ? v0 : 0.2f * v0;
    float v1 = as.y + ad.y; v1 = v1 > 0.f ? v1 : 0.2f * v1;
    float w0 = expf(v0), w1 = expf(v1);
    *(float2*)(d_w + (size_t)e * 2) = make_float2(w0, w1);
    redv2(d_den + (size_t)d * 2, w0, w1);
}

// Scatter into node-major d_g: contiguous 48 floats per node (3 sectors/edge).
__global__ void k_passC(const int* __restrict__ ei, int E) {
    int idx = blockIdx.x * blockDim.x + threadIdx.x;
    int etot = E + NTOT;
    if (idx >= etot * 12) return;
    int e = idx / 12, q = idx - e * 12;
    int s, d; edge_sd(ei, E, e, s, d);
    float2 a  = *(const float2*)(d_w + (size_t)e * 2);
    float2 dn = *(const float2*)(d_den + (size_t)d * 2);
    float a0 = a.x * __fdividef(0.5f, dn.x + 1e-16f);
    float a1 = a.y * __fdividef(0.5f, dn.y + 1e-16f);
    const float4 h0 = *(const float4*)(d_h + (size_t)s * 96 + q * 4);
    const float4 h1 = *(const float4*)(d_h + (size_t)s * 96 + 48 + q * 4);
    float vx = fmaf(a0, h0.x, a1 * h1.x);
    float vy = fmaf(a0, h0.y, a1 * h1.y);
    float vz = fmaf(a0, h0.z, a1 * h1.z);
    float vw = fmaf(a0, h0.w, a1 * h1.w);
    redv4(d_g + (size_t)d * 48 + q * 4, vx, vy, vz, vw);
}

// Reshape d_g [node][48] -> d_xin [m = b*12+t][4n+f] (both sides coalesced via smem).
// Grid: 512 blocks (8 per batch), 256 threads. 125 nodes per block.
__global__ __launch_bounds__(256) void k_reshape() {
    __shared__ float gs[125][49];                // stride 49: conflict-free column reads
    int b = blockIdx.x >> 3;
    int n0 = (blockIdx.x & 7) * 125;
    int tid = threadIdx.x;
    const float* src = d_g + ((size_t)b * NN + n0) * 48;
    for (int i = tid; i < 125 * 48; i += 256)
        gs[i / 48][i % 48] = src[i];
    __syncthreads();
    for (int idx = tid; idx < 12 * 125; idx += 256) {
        int t = idx / 125, i = idx - t * 125;
        float4 v = make_float4(gs[i][4 * t], gs[i][4 * t + 1],
                               gs[i][4 * t + 2], gs[i][4 * t + 3]);
        *(float4*)(d_xin + ((size_t)(b * SEQL + t)) * D1 + (size_t)(n0 + i) * 4) = v;
    }
}

// NT SGEMM v3: 8x8 microtile (2B LDS per fma2 -> LDS floor == fma2 floor).
// Tile 64(M) x 128(N), 128 threads. A = d_xin (contig), B = d_wih1T (coalesced).
// C = d_xw1 (zeroed), split-K via blockIdx.z, red-v4 epilogue. Row m = b*12+t.
__global__ __launch_bounds__(128) void k_sgemm1() {
    const int K = D1, N = G1;
    __shared__ __align__(16) float As[16][68];
    __shared__ __align__(16) float Bs[16][132];
    int tid = threadIdx.x;
    int tx = tid & 15;            // 0..15 -> 8 cols each (128 n)
    int ty = tid >> 4;            // 0..7  -> 8 rows each (64 m)
    int m0 = blockIdx.y * 64;
    int n0 = blockIdx.x * 128;
    int klen = K / SPLITK;        // 400
    int kbeg = blockIdx.z * klen;

    ull acc2[8][4];
#pragma unroll
    for (int i = 0; i < 8; i++)
#pragma unroll
        for (int j = 0; j < 4; j++) acc2[i][j] = 0ULL;

    for (int k0 = kbeg; k0 < kbeg + klen; k0 += 16) {
        // A: 64 rows x 16 k = 256 float4 (coalesced 64B/row)
#pragma unroll
        for (int l = 0; l < 2; l++) {
            int lin = tid + l * 128;
            int mm = lin >> 2, kq = lin & 3;
            float4 av = *(const float4*)(d_xin + (size_t)(m0 + mm) * K + k0 + kq * 4);
            As[kq * 4 + 0][mm] = av.x; As[kq * 4 + 1][mm] = av.y;
            As[kq * 4 + 2][mm] = av.z; As[kq * 4 + 3][mm] = av.w;
        }
        // B: 16 rows x 128 n = 512 float4 (coalesced 512B/row)
#pragma unroll
        for (int l = 0; l < 4; l++) {
            int lin = tid + l * 128;
            int kk = lin >> 5, nq = lin & 31;
            float4 bv = *(const float4*)(d_wih1T + (size_t)(kbeg + (k0 - kbeg) + kk) * N
                                         + n0 + nq * 4);
            // (k0 + kk) written explicitly to avoid any confusion:
            (void)bv;
            bv = *(const float4*)(d_wih1T + (size_t)(k0 + kk) * N + n0 + nq * 4);
            *(float4*)&Bs[kk][nq * 4] = bv;
        }
        __syncthreads();
#pragma unroll
        for (int kk = 0; kk < 16; kk++) {
            float4 aA = *(const float4*)&As[kk][ty * 8];
            float4 aB = *(const float4*)&As[kk][ty * 8 + 4];
            ulonglong2 bL = *(const ulonglong2*)&Bs[kk][tx * 8];
            ulonglong2 bH = *(const ulonglong2*)&Bs[kk][tx * 8 + 4];
            ull b0 = bL.x, b1 = bL.y, b2 = bH.x, b3 = bH.y;
            ull ad0 = pack2(aA.x, aA.x), ad1 = pack2(aA.y, aA.y);
            ull ad2 = pack2(aA.z, aA.z), ad3 = pack2(aA.w, aA.w);
            ull ad4 = pack2(aB.x, aB.x), ad5 = pack2(aB.y, aB.y);
            ull ad6 = pack2(aB.z, aB.z), ad7 = pack2(aB.w, aB.w);
            fma2(acc2[0][0], ad0, b0); fma2(acc2[0][1], ad0, b1);
            fma2(acc2[0][2], ad0, b2); fma2(acc2[0][3], ad0, b3);
            fma2(acc2[1][0], ad1, b0); fma2(acc2[1][1], ad1, b1);
            fma2(acc2[1][2], ad1, b2); fma2(acc2[1][3], ad1, b3);
            fma2(acc2[2][0], ad2, b0); fma2(acc2[2][1], ad2, b1);
            fma2(acc2[2][2], ad2, b2); fma2(acc2[2][3], ad2, b3);
            fma2(acc2[3][0], ad3, b0); fma2(acc2[3][1], ad3, b1);
            fma2(acc2[3][2], ad3, b2); fma2(acc2[3][3], ad3, b3);
            fma2(acc2[4][0], ad4, b0); fma2(acc2[4][1], ad4, b1);
            fma2(acc2[4][2], ad4, b2); fma2(acc2[4][3], ad4, b3);
            fma2(acc2[5][0], ad5, b0); fma2(acc2[5][1], ad5, b1);
            fma2(acc2[5][2], ad5, b2); fma2(acc2[5][3], ad5, b3);
            fma2(acc2[6][0], ad6, b0); fma2(acc2[6][1], ad6, b1);
            fma2(acc2[6][2], ad6, b2); fma2(acc2[6][3], ad6, b3);
            fma2(acc2[7][0], ad7, b0); fma2(acc2[7][1], ad7, b1);
            fma2(acc2[7][2], ad7, b2); fma2(acc2[7][3], ad7, b3);
        }
        __syncthreads();
    }
#pragma unroll
    for (int i = 0; i < 8; i++) {
        int m = m0 + ty * 8 + i;
        float* cr = d_xw1 + (size_t)m * N + n0 + tx * 8;
        float2 u0 = unpack2(acc2[i][0]), u1 = unpack2(acc2[i][1]);
        float2 u2 = unpack2(acc2[i][2]), u3 = unpack2(acc2[i][3]);
        redv4(cr,     u0.x, u0.y, u1.x, u1.y);
        redv4(cr + 4, u2.x, u2.y, u3.x, u3.y);
    }
}

// Prep: W_ih1 col-sums (blocks < G1) + recurrent weight transposes (rest).
__global__ void k_prep(const float* __restrict__ Wih1, const float* __restrict__ W1,
                       const float* __restrict__ W2, const float* __restrict__ W3) {
    if (blockIdx.x < G1) {
        __shared__ float part[256];
        int j = blockIdx.x;
        const float* wr = Wih1 + (size_t)j * D1;
        float acc = 0.f;
        for (int e = threadIdx.x; e < D1; e += 256) acc += __ldg(wr + e);  // f = e&3 fixed
        part[threadIdx.x] = acc;
        __syncthreads();
        if (threadIdx.x < 4) {
            float s = 0.f;
            for (int i = threadIdx.x; i < 256; i += 4) s += part[i];
            d_ws[j * 4 + threadIdx.x] = s;
        }
        return;
    }
    int idx = (blockIdx.x - G1) * 256 + threadIdx.x;
    if (idx < G1 * H1S) {                                   // whh1T
        int k = idx / G1, j = idx % G1;
        d_whh1T[idx] = W1[(size_t)j * H1S + k];
    } else if (idx < G1 * H1S + G2 * H2S) {                 // whh2T
        int r = idx - G1 * H1S;
        int k = r / G2, j = r % G2;
        d_whh2T[r] = W2[(size_t)j * H2S + k];
    } else if (idx < G1 * H1S + G2 * H2S + G2 * H1S) {      // wih2T
        int r = idx - G1 * H1S - G2 * H2S;
        int k = r / G2, j = r % G2;
        d_wih2T[r] = W3[(size_t)j * H1S + k];
    }
}

// ============ pipelined LSTM: launch s runs step1(t=s) [blocks 0..63] and
// step2(t=s-1) [blocks 64..95] concurrently. h1 double-buffered by t parity. ====
__global__ __launch_bounds__(256) void k_pipe(
    int s, const float* __restrict__ b1, const float* __restrict__ gbias,
    const float* __restrict__ b2v)
{
    __shared__ __align__(16) float hs1[H1S][16];
    __shared__ __align__(16) float hs2[H2S][16];
    __shared__ float gsm[64][17];
    int tid = threadIdx.x;

    if (blockIdx.x < 64) {
        // ---------- layer 1, t = s ----------
        if (s >= SEQL) return;
        int t = s;
        int u0 = (blockIdx.x & 15) * 16;
        int b0 = (blockIdx.x >> 4) * 16;
        const float* hR = d_state + (t & 1) * (H1S * NB);
        float*       hW = d_state + ((t + 1) & 1) * (H1S * NB);
        float*       c1 = d_state + 2 * (H1S * NB);

        for (int i = tid; i < H1S * 16; i += 256)
            hs1[i >> 4][i & 15] = hR[(i >> 4) * NB + b0 + (i & 15)];
        __syncthreads();

        int jj = tid & 63, bq = tid >> 6;
        int j = (jj >> 4) * H1S + u0 + (jj & 15);
        ull a01 = 0, a23 = 0;
        const float* wp = d_whh1T + j;
#pragma unroll 8
        for (int k = 0; k < H1S; k++) {
            float w = wp[k * G1];
            ull wd = pack2(w, w);
            const ull* hp = (const ull*)&hs1[k][bq * 4];
            fma2(a01, wd, hp[0]);
            fma2(a23, wd, hp[1]);
        }
        {
            float bias = __ldg(b1 + j);
            float4 wsv = *(const float4*)(d_ws + j * 4);
            float4 gb  = *(const float4*)(gbias + 4 * t);
            bias = fmaf(gb.x, wsv.x, fmaf(gb.y, wsv.y,
                   fmaf(gb.z, wsv.z, fmaf(gb.w, wsv.w, bias))));
            float2 u01 = unpack2(a01), u23 = unpack2(a23);
            float gv4[4] = {u01.x, u01.y, u23.x, u23.y};
#pragma unroll
            for (int i = 0; i < 4; i++) {
                int b = b0 + bq * 4 + i;
                gsm[jj][bq * 4 + i] = gv4[i] + bias
                                    + d_xw1[((size_t)(b * SEQL + t)) * G1 + j];
            }
        }
        __syncthreads();
        {
            int bl = tid & 15, ul = tid >> 4;
            float iv = sigf(gsm[ul][bl]);
            float fv = sigf(gsm[16 + ul][bl]);
            float gv = tanhf(gsm[32 + ul][bl]);
            float ov = sigf(gsm[48 + ul][bl]);
            int ci = (u0 + ul) * NB + b0 + bl;
            float c = fv * c1[ci] + iv * gv;
            c1[ci] = c;
            hW[ci] = ov * tanhf(c);
        }
    } else {
        // ---------- layer 2, t = s-1 ----------
        if (s < 1) return;
        int t = s - 1;
        int r = blockIdx.x - 64;
        int u0 = (r & 7) * 16;
        int b0 = (r >> 3) * 16;
        const float* h1v = d_state + ((t + 1) & 1) * (H1S * NB);
        float*       h2  = d_state + 3 * (H1S * NB);
        float*       c2  = d_state + 3 * (H1S * NB) + H2S * NB;

        for (int i = tid; i < H1S * 16; i += 256)
            hs1[i >> 4][i & 15] = h1v[(i >> 4) * NB + b0 + (i & 15)];
        for (int i = tid; i < H2S * 16; i += 256)
            hs2[i >> 4][i & 15] = h2[(i >> 4) * NB + b0 + (i & 15)];
        __syncthreads();

        int jj = tid & 63, bq = tid >> 6;
        int j = (jj >> 4) * H2S + u0 + (jj & 15);
        ull a01 = 0, a23 = 0;
        const float* wp = d_wih2T + j;
#pragma unroll 8
        for (int k = 0; k < H1S; k++) {
            float w = wp[k * G2];
            ull wd = pack2(w, w);
            const ull* hp = (const ull*)&hs1[k][bq * 4];
            fma2(a01, wd, hp[0]);
            fma2(a23, wd, hp[1]);
        }
        const float* wq = d_whh2T + j;
#pragma unroll 8
        for (int k = 0; k < H2S; k++) {
            float w = wq[k * G2];
            ull wd = pack2(w, w);
            const ull* hp = (const ull*)&hs2[k][bq * 4];
            fma2(a01, wd, hp[0]);
            fma2(a23, wd, hp[1]);
        }
        {
            float bb = __ldg(b2v + j);
            float2 u01 = unpack2(a01), u23 = unpack2(a23);
            gsm[jj][bq * 4 + 0] = u01.x + bb;
            gsm[jj][bq * 4 + 1] = u01.y + bb;
            gsm[jj][bq * 4 + 2] = u23.x + bb;
            gsm[jj][bq * 4 + 3] = u23.y + bb;
        }
        __syncthreads();
        {
            int bl = tid & 15, ul = tid >> 4;
            float iv = sigf(gsm[ul][bl]);
            float fv = sigf(gsm[16 + ul][bl]);
            float gv = tanhf(gsm[32 + ul][bl]);
            float ov = sigf(gsm[48 + ul][bl]);
            int ci = (u0 + ul) * NB + b0 + bl;
            float c = fv * c2[ci] + iv * gv;
            c2[ci] = c;
            h2[ci] = ov * tanhf(c);
        }
    }
}

// out[b*2000 + j] = sum_k h2[k][b] * W_out[j,k] + b_out[j]
__global__ void k_out(const float* __restrict__ Wo, const float* __restrict__ bo,
                      float* __restrict__ out) {
    __shared__ __align__(16) float hr[H2S];
    const float* h2 = d_state + 3 * (H1S * NB);
    int b = blockIdx.y;
    if (threadIdx.x < H2S) hr[threadIdx.x] = h2[threadIdx.x * NB + b];
    __syncthreads();
    int j = blockIdx.x * blockDim.x + threadIdx.x;
    if (j >= NN * 2) return;
    const ull* wp = (const ull*)(Wo + (size_t)j * H2S);
    const ull* hp = (const ull*)hr;
    ull accA = 0, accB = 0;
#pragma unroll 8
    for (int k = 0; k < H2S / 2; k += 2) {
        fma2(accA, hp[k], wp[k]);
        fma2(accB, hp[k + 1], wp[k + 1]);
    }
    float2 uA = unpack2(accA), uB = unpack2(accB);
    out[(size_t)b * (NN * 2) + j] = uA.x + uA.y + uB.x + uB.y + __ldg(bo + j);
}

// ---------------- launch ----------------
extern "C" void kernel_launch(void* const* d_in, const int* in_sizes, int n_in,
                              void* d_out, int out_size) {
    const float* x     = (const float*)d_in[0];
    const int*   ei    = (const int*)d_in[1];     // int32 (JAX x64 disabled)
    const float* Wg    = (const float*)d_in[2];
    const float* att_s = (const float*)d_in[3];
    const float* att_d = (const float*)d_in[4];
    const float* gbias = (const float*)d_in[5];
    const float* Wih1  = (const float*)d_in[6];
    const float* Whh1  = (const float*)d_in[7];
    const float* b1    = (const float*)d_in[8];
    const float* Wih2  = (const float*)d_in[9];
    const float* Whh2  = (const float*)d_in[10];
    const float* b2    = (const float*)d_in[11];
    const float* Wo    = (const float*)d_in[12];
    const float* bo    = (const float*)d_in[13];
    float* out = (float*)d_out;

    int E = in_sizes[1] / 2;
    if (E > EMAX) E = EMAX;
    int etot = E + NTOT;

    // ncu captures launch #4 -> k_reshape profiled this round (new kernel).
    k_gemm_attn<<<NTOT / 64 + 125, 256>>>(x, Wg, att_s, att_d, Wih1); // 1
    k_passAB<<<(etot + 255) / 256, 256>>>(ei, E);                     // 2
    k_passC<<<(etot * 12 + 255) / 256, 256>>>(ei, E);                 // 3
    k_reshape<<<NB * 8, 256>>>();                                     // 4  <- profiled
    k_sgemm1<<<dim3(G1 / 128, TBR / 64, SPLITK), 128>>>();            // 5

    int tblocks = (G1 * H1S + G2 * H2S + G2 * H1S + 255) / 256;
    k_prep<<<G1 + tblocks, 256>>>(Wih1, Whh1, Whh2, Wih2);            // 6

    for (int s = 0; s <= SEQL; s++)                                   // 7..19
        k_pipe<<<96, 256>>>(s, b1, gbias, b2);

    k_out<<<dim3((NN * 2 + 255) / 256, NB), 256>>>(Wo, bo, out);      // 20
}